// round 16
// baseline (speedup 1.0000x reference)
#include <cuda_runtime.h>
#include <cuda_fp16.h>
#include <math.h>
#include <stdint.h>

#define BATCH    2
#define SEQ      2048
#define HID      2048
#define NKH      16
#define NVH      32
#define DKH      128
#define DVH      128
#define QKD      2048
#define VDD      4096
#define CI       8192
#define KCONV    4

#define OUT_OFF_CONV  (BATCH*SEQ*HID)
#define OUT_OFF_STATE (OUT_OFF_CONV + BATCH*CI*KCONV)

typedef unsigned long long u64;

__device__ float  g_qkv_raw[(size_t)BATCH*CI*SEQ];
__device__ float  g_conv   [(size_t)BATCH*SEQ*CI];
__device__ float  g_z      [(size_t)BATCH*SEQ*VDD];
__device__ float2 g_egbt   [(size_t)BATCH*SEQ*NVH];
__device__ float  g_y      [(size_t)BATCH*SEQ*NVH*DVH];
__device__ __half g_xh     [(size_t)BATCH*SEQ*HID];
__device__ __half g_wqkvh  [(size_t)CI*HID];
__device__ __half g_wzh    [(size_t)VDD*HID];
__device__ __half g_wouth  [(size_t)HID*VDD];
__device__ __half g_youth  [(size_t)BATCH*SEQ*VDD];

// ---------------- float -> half conversion ----------------
__global__ void f2h_kernel(const float* __restrict__ in, __half* __restrict__ out)
{
    size_t i = ((size_t)blockIdx.x * 256 + threadIdx.x) * 4;
    float4 v = *(const float4*)(in + i);
    __half2 a = __floats2half2_rn(v.x, v.y);
    __half2 b = __floats2half2_rn(v.z, v.w);
    *(uint2*)(out + i) = make_uint2(*(uint32_t*)&a, *(uint32_t*)&b);
}

// ------------------------------------------------------------------
// FP16 tensor-core GEMM, K-chunk 32, ldmatrix fragment loads.
// mode 0: C row-major. mode 1: C[b][m][s], n = b*SEQ+s (n_base offsets grid.x)
// ------------------------------------------------------------------
__device__ __forceinline__ void mma_f16(float* c, const uint32_t* a, const uint32_t* b) {
    asm volatile(
        "mma.sync.aligned.m16n8k16.row.col.f32.f16.f16.f32 "
        "{%0,%1,%2,%3}, {%4,%5,%6,%7}, {%8,%9}, {%0,%1,%2,%3};"
        : "+f"(c[0]), "+f"(c[1]), "+f"(c[2]), "+f"(c[3])
        : "r"(a[0]), "r"(a[1]), "r"(a[2]), "r"(a[3]), "r"(b[0]), "r"(b[1]));
}

__device__ __forceinline__ void ldsm_x4(uint32_t* r, uint32_t addr) {
    asm volatile(
        "ldmatrix.sync.aligned.m8n8.x4.shared.b16 {%0,%1,%2,%3}, [%4];"
        : "=r"(r[0]), "=r"(r[1]), "=r"(r[2]), "=r"(r[3]) : "r"(addr));
}

__global__ __launch_bounds__(128, 2)
void gemm_h(const __half* __restrict__ A, const __half* __restrict__ Bm,
            float* __restrict__ C, int M, int N, int K, int mode, int n_base)
{
    __shared__ uint32_t As[2][128][20];
    __shared__ uint32_t Bs[2][128][20];

    const int tid = threadIdx.x, lane = tid & 31, wid = tid >> 5;
    const int m0 = blockIdx.y * 128, n0 = blockIdx.x * 128 + n_base;
    const int wm = (wid & 1) * 64, wn = (wid >> 1) * 64;

    const int lrow = tid >> 2;
    const int lc   = tid & 3;

    const __half* Ap = A  + (size_t)(m0 + lrow) * K + lc * 8;
    const __half* Bp = Bm + (size_t)(n0 + lrow) * K + lc * 8;

    const uint32_t asBase = (uint32_t)__cvta_generic_to_shared(&As[0][0][0]);
    const uint32_t bsBase = (uint32_t)__cvta_generic_to_shared(&Bs[0][0][0]);
    const uint32_t bufOff = 128 * 20 * 4;

    const int aRowOff = (wm + ((lane >> 3) & 1) * 8 + (lane & 7)) * 20
                      + ((lane >> 4) & 1) * 4;
    const int bRowOff = (wn + (lane >> 4) * 8 + (lane & 7)) * 20
                      + ((lane >> 3) & 1) * 4;

    float acc[4][8][4];
#pragma unroll
    for (int mi = 0; mi < 4; mi++)
#pragma unroll
        for (int ni = 0; ni < 8; ni++)
#pragma unroll
            for (int t = 0; t < 4; t++) acc[mi][ni][t] = 0.f;

    uint4 va[4], vb[4];
#pragma unroll
    for (int i = 0; i < 4; i++) {
        va[i] = *(const uint4*)(Ap + (size_t)(32 * i) * K);
        vb[i] = *(const uint4*)(Bp + (size_t)(32 * i) * K);
    }

    const int nch = K >> 5;

#pragma unroll
    for (int i = 0; i < 4; i++) {
        *(uint4*)&As[0][lrow + 32 * i][lc * 4] = va[i];
        *(uint4*)&Bs[0][lrow + 32 * i][lc * 4] = vb[i];
    }
    __syncthreads();

    const int g  = lane >> 2;
    const int kk = lane & 3;

    for (int c = 0; c < nch; c++) {
        const int buf = c & 1;
        const bool more = (c + 1 < nch);

        if (more) {
            const int ko = (c + 1) * 32;
#pragma unroll
            for (int i = 0; i < 4; i++) {
                va[i] = *(const uint4*)(Ap + (size_t)(32 * i) * K + ko);
                vb[i] = *(const uint4*)(Bp + (size_t)(32 * i) * K + ko);
            }
        }

        const uint32_t aB = asBase + buf * bufOff;
        const uint32_t bB = bsBase + buf * bufOff;

#pragma unroll
        for (int t = 0; t < 2; t++) {
            uint32_t af[4][4];
#pragma unroll
            for (int mi = 0; mi < 4; mi++)
                ldsm_x4(af[mi], aB + (uint32_t)(aRowOff + mi * 16 * 20 + t * 8) * 4);
            uint32_t bf[8][2];
#pragma unroll
            for (int p = 0; p < 4; p++) {
                uint32_t br[4];
                ldsm_x4(br, bB + (uint32_t)(bRowOff + p * 16 * 20 + t * 8) * 4);
                bf[2*p][0]   = br[0];
                bf[2*p][1]   = br[1];
                bf[2*p+1][0] = br[2];
                bf[2*p+1][1] = br[3];
            }
#pragma unroll
            for (int mi = 0; mi < 4; mi++)
#pragma unroll
                for (int ni = 0; ni < 8; ni++)
                    mma_f16(acc[mi][ni], af[mi], bf[ni]);
        }

        if (more) {
            const int ob = buf ^ 1;
#pragma unroll
            for (int i = 0; i < 4; i++) {
                *(uint4*)&As[ob][lrow + 32 * i][lc * 4] = va[i];
                *(uint4*)&Bs[ob][lrow + 32 * i][lc * 4] = vb[i];
            }
        }
        __syncthreads();
    }

#pragma unroll
    for (int mi = 0; mi < 4; mi++) {
        const int grow = m0 + wm + mi * 16 + g;
#pragma unroll
        for (int ni = 0; ni < 8; ni++) {
            const int gcol = n0 + wn + ni * 8 + kk * 2;
            if (mode == 0) {
                *(float2*)(C + (size_t)grow * N + gcol) =
                    make_float2(acc[mi][ni][0], acc[mi][ni][1]);
                *(float2*)(C + (size_t)(grow + 8) * N + gcol) =
                    make_float2(acc[mi][ni][2], acc[mi][ni][3]);
            } else {
                const int bi = gcol >> 11;
                const int sc = gcol & 2047;
                float* base = C + (size_t)bi * M * SEQ + sc;
                *(float2*)(base + (size_t)grow * SEQ) =
                    make_float2(acc[mi][ni][0], acc[mi][ni][1]);
                *(float2*)(base + (size_t)(grow + 8) * SEQ) =
                    make_float2(acc[mi][ni][2], acc[mi][ni][3]);
            }
        }
    }
}

// ------------------------------------------------------------------
__global__ __launch_bounds__(256)
void ab_kernel(const float* __restrict__ X, const float* __restrict__ Wa,
               const float* __restrict__ Wb, const float* __restrict__ A_log,
               const float* __restrict__ dt_bias)
{
    __shared__ float xs[4][HID];
    const int row0 = blockIdx.x * 4;
    for (int i = threadIdx.x; i < 4 * HID; i += 256)
        xs[i >> 11][i & 2047] = X[(size_t)(row0 + (i >> 11)) * HID + (i & 2047)];
    __syncthreads();

    const int w = threadIdx.x >> 5;
    const int lane = threadIdx.x & 31;
#pragma unroll 1
    for (int oi = 0; oi < 8; oi++) {
        int n = w * 8 + oi;
        const float* Wp = (n < 32) ? (Wa + (size_t)n * HID) : (Wb + (size_t)(n - 32) * HID);
        float a0 = 0.f, a1 = 0.f, a2 = 0.f, a3 = 0.f;
        for (int i = lane; i < HID; i += 32) {
            float wv = Wp[i];
            a0 = fmaf(xs[0][i], wv, a0);
            a1 = fmaf(xs[1][i], wv, a1);
            a2 = fmaf(xs[2][i], wv, a2);
            a3 = fmaf(xs[3][i], wv, a3);
        }
#pragma unroll
        for (int off = 16; off; off >>= 1) {
            a0 += __shfl_xor_sync(0xffffffffu, a0, off);
            a1 += __shfl_xor_sync(0xffffffffu, a1, off);
            a2 += __shfl_xor_sync(0xffffffffu, a2, off);
            a3 += __shfl_xor_sync(0xffffffffu, a3, off);
        }
        if (lane == 0) {
            float av[4] = {a0, a1, a2, a3};
            if (n < 32) {
                float al = expf(A_log[n]);
                float db = dt_bias[n];
#pragma unroll
                for (int r = 0; r < 4; r++) {
                    float x = av[r] + db;
                    float sp = (x > 20.f) ? x : log1pf(expf(x));
                    g_egbt[(size_t)(row0 + r) * NVH + n].x = expf(-al * sp);
                }
            } else {
#pragma unroll
                for (int r = 0; r < 4; r++)
                    g_egbt[(size_t)(row0 + r) * NVH + (n - 32)].y = 1.f / (1.f + expf(-av[r]));
            }
        }
    }
}

__global__ void convstate_kernel(float* __restrict__ outc)
{
    int idx = blockIdx.x * 256 + threadIdx.x;
    int b = idx >> 15;
    int rem = idx & 32767;
    int c = rem >> 2;
    int jj = rem & 3;
    outc[idx] = g_qkv_raw[(size_t)b * CI * SEQ + (size_t)c * SEQ + (SEQ - KCONV) + jj];
}

__global__ __launch_bounds__(256)
void convnorm_kernel(const float* __restrict__ w, int b)
{
    __shared__ float in_sm[128][37];
    __shared__ float out_sm[32][132];
    const int s0 = blockIdx.x * 32;
    const int cb = blockIdx.y;
    const int c0 = cb * 128;
    const float* rp = g_qkv_raw + (size_t)b * CI * SEQ + (size_t)c0 * SEQ;

    for (int idx = threadIdx.x; idx < 128 * 35; idx += 256) {
        int cl = idx / 35, sl = idx % 35;
        int s = s0 - 3 + sl;
        in_sm[cl][sl] = (s >= 0) ? rp[(size_t)cl * SEQ + s] : 0.f;
    }
    __syncthreads();

    {
        const int cl = threadIdx.x & 127;
        const int sh = threadIdx.x >> 7;
        const int c  = c0 + cl;
        const float w0 = w[c*4+0], w1 = w[c*4+1], w2 = w[c*4+2], w3 = w[c*4+3];
#pragma unroll
        for (int i = 0; i < 16; i++) {
            int sl = sh * 16 + i;
            float acc = in_sm[cl][sl] * w0 + in_sm[cl][sl+1] * w1
                      + in_sm[cl][sl+2] * w2 + in_sm[cl][sl+3] * w3;
            out_sm[sl][cl] = acc / (1.f + expf(-acc));
        }
    }
    __syncthreads();

    const int wld = threadIdx.x >> 5;
    const int lane = threadIdx.x & 31;
    const bool isqk = (cb < 32);
    const float qs = (cb < 16) ? 0.08838834764831845f : 1.0f;
    float* gout = g_conv + (size_t)b * SEQ * CI + c0;
#pragma unroll
    for (int t = 0; t < 4; t++) {
        int sl = wld * 4 + t;
        float4 v4 = *(float4*)&out_sm[sl][lane * 4];
        if (isqk) {
            float ss = v4.x*v4.x + v4.y*v4.y + v4.z*v4.z + v4.w*v4.w;
#pragma unroll
            for (int off = 16; off; off >>= 1) ss += __shfl_xor_sync(0xffffffffu, ss, off);
            float r = rsqrtf(ss + 1e-6f) * qs;
            v4.x *= r; v4.y *= r; v4.z *= r; v4.w *= r;
        }
        *(float4*)(gout + (size_t)(s0 + sl) * CI + lane * 4) = v4;
    }
}

// ------------------------------------------------------------------
// delta-rule scan (R11 config): 2 v-rows/thread, merged single
// shfl-tree reductions, f32x2 FMA, 2-step pipeline. Per-batch launch.
// ------------------------------------------------------------------
#define FMA2(d, a, b, c) \
    asm("fma.rn.f32x2 %0, %1, %2, %3;" : "=l"(d) : "l"(a), "l"(b), "l"(c))
#define MUL2(d, a, b) \
    asm("mul.rn.f32x2 %0, %1, %2;" : "=l"(d) : "l"(a), "l"(b))
#define PACK2(d, x) \
    asm("mov.b64 %0, {%1, %1};" : "=l"(d) : "r"(__float_as_uint(x)))
#define UNPACK2(lo, hi, s) \
    asm("mov.b64 {%0, %1}, %2;" : "=r"(lo), "=r"(hi) : "l"(s))

__device__ __forceinline__ float pairsum(u64 p) {
    uint32_t lo, hi;
    UNPACK2(lo, hi, p);
    return __uint_as_float(lo) + __uint_as_float(hi);
}

#define SCAN_LOAD(krp, qrp, vv, eb, s)                                          \
    do {                                                                        \
        const float* _rp = cb + (size_t)(s) * CI;                               \
        _Pragma("unroll")                                                       \
        for (int _g = 0; _g < 4; _g++) {                                        \
            *(ulonglong2*)((krp) + 2*_g) = *(const ulonglong2*)(_rp + koff + _g*32); \
            *(ulonglong2*)((qrp) + 2*_g) = *(const ulonglong2*)(_rp + qoff + _g*32); \
        }                                                                        \
        (vv) = *(const float2*)(_rp + voff);                                    \
        (eb) = ebp[(size_t)(s) * NVH];                                          \
    } while (0)

#define SCAN_STEP(krp, qrp, vv, eb, s)                                          \
    do {                                                                        \
        u64 kv0p = 0ull, kv1p = 0ull, qs0p = 0ull, qs1p = 0ull, qkp = 0ull;     \
        _Pragma("unroll")                                                       \
        for (int i = 0; i < 8; i++) {                                           \
            FMA2(kv0p, stp0[i], (krp)[i], kv0p);                                \
            FMA2(kv1p, stp1[i], (krp)[i], kv1p);                                \
            FMA2(qs0p, stp0[i], (qrp)[i], qs0p);                                \
            FMA2(qs1p, stp1[i], (qrp)[i], qs1p);                                \
            FMA2(qkp,  (krp)[i], (qrp)[i], qkp);                                \
        }                                                                        \
        float kv0 = pairsum(kv0p), kv1 = pairsum(kv1p);                         \
        float qs0 = pairsum(qs0p), qs1 = pairsum(qs1p);                         \
        float qk  = pairsum(qkp);                                               \
        _Pragma("unroll")                                                       \
        for (int off = 1; off <= 4; off <<= 1) {                                \
            kv0 += __shfl_xor_sync(0xffffffffu, kv0, off);                      \
            kv1 += __shfl_xor_sync(0xffffffffu, kv1, off);                      \
            qs0 += __shfl_xor_sync(0xffffffffu, qs0, off);                      \
            qs1 += __shfl_xor_sync(0xffffffffu, qs1, off);                      \
            qk  += __shfl_xor_sync(0xffffffffu, qk,  off);                      \
        }                                                                        \
        const float eg = (eb).x, bt = (eb).y;                                   \
        const float d0 = ((vv).x - eg * kv0) * bt;                              \
        const float d1 = ((vv).y - eg * kv1) * bt;                              \
        if (j == 0) {                                                           \
            float o0 = eg * qs0 + d0 * qk;                                      \
            float o1 = eg * qs1 + d1 * qk;                                      \
            *(float2*)(yp + (size_t)(s) * (NVH * 128)) = make_float2(o0, o1);   \
        }                                                                        \
        u64 egp, d0p, d1p;                                                      \
        PACK2(egp, eg);                                                         \
        PACK2(d0p, d0);                                                         \
        PACK2(d1p, d1);                                                         \
        _Pragma("unroll")                                                       \
        for (int i = 0; i < 8; i++) {                                           \
            u64 t0, t1;                                                         \
            MUL2(t0, (krp)[i], d0p);                                            \
            MUL2(t1, (krp)[i], d1p);                                            \
            FMA2(stp0[i], stp0[i], egp, t0);                                    \
            FMA2(stp1[i], stp1[i], egp, t1);                                    \
        }                                                                        \
    } while (0)

__global__ __launch_bounds__(128)
void scan_kernel(float* __restrict__ state_out, int b)
{
    const int gt = blockIdx.x * 128 + threadIdx.x;   // 16384 threads (one batch)
    const int j = gt & 7;
    const int rowi = gt >> 3;        // 0..2047
    const int vp = rowi & 63;
    const int h = rowi >> 6;         // 0..31
    const int kh = h >> 1;
    const int v0 = vp * 2;

    u64 stp0[8], stp1[8];
#pragma unroll
    for (int i = 0; i < 8; i++) { stp0[i] = 0ull; stp1[i] = 0ull; }

    const float* cb = g_conv + (size_t)b * SEQ * CI;
    const float2* ebp = g_egbt + (size_t)b * SEQ * NVH + h;
    const int qoff = kh * 128 + j * 4;
    const int koff = QKD + kh * 128 + j * 4;
    const int voff = 2 * QKD + h * 128 + v0;
    float* yp = g_y + ((size_t)b * SEQ * NVH + h) * 128 + v0;

    u64 krA[8], qrA[8], krB[8], qrB[8];
    float2 vvA, vvB, ebA, ebB;

    SCAN_LOAD(krA, qrA, vvA, ebA, 0);

    for (int s = 0; s < SEQ; s += 2) {
        SCAN_LOAD(krB, qrB, vvB, ebB, s + 1);
        SCAN_STEP(krA, qrA, vvA, ebA, s);
        if (s + 2 < SEQ) SCAN_LOAD(krA, qrA, vvA, ebA, s + 2);
        SCAN_STEP(krB, qrB, vvB, ebB, s + 1);
    }

    float* so0 = state_out + (((size_t)(b * NVH + h) * 128) + v0) * 128 + j * 4;
    float* so1 = so0 + 128;
#pragma unroll
    for (int g = 0; g < 4; g++) {
        *(ulonglong2*)(so0 + g * 32) = make_ulonglong2(stp0[2*g], stp0[2*g+1]);
        *(ulonglong2*)(so1 + g * 32) = make_ulonglong2(stp1[2*g], stp1[2*g+1]);
    }
}

__global__ __launch_bounds__(256)
void rms_gate_kernel(const float* __restrict__ nw, int gbase)
{
    const int gidx = gbase + blockIdx.x * 8 + (threadIdx.x >> 5);
    const int lane = threadIdx.x & 31;
    const float* yv4 = g_y + (size_t)gidx * 128 + lane * 4;
    float4 yv = *(const float4*)yv4;
    float ss = yv.x*yv.x + yv.y*yv.y + yv.z*yv.z + yv.w*yv.w;
#pragma unroll
    for (int off = 16; off; off >>= 1) ss += __shfl_xor_sync(0xffffffffu, ss, off);
    const float r = rsqrtf(ss * (1.f / 128.f) + 1e-6f);
    const size_t zoff = ((size_t)(gidx >> 5)) * VDD + (size_t)(gidx & 31) * 128 + lane * 4;
    float4 zv = *(const float4*)(g_z + zoff);
    float4 nv = *(const float4*)(nw + lane * 4);
    float ox = nv.x * yv.x * r * (zv.x / (1.f + expf(-zv.x)));
    float oy = nv.y * yv.y * r * (zv.y / (1.f + expf(-zv.y)));
    float oz = nv.z * yv.z * r * (zv.z / (1.f + expf(-zv.z)));
    float ow = nv.w * yv.w * r * (zv.w / (1.f + expf(-zv.w)));
    __half2 h01 = __floats2half2_rn(ox, oy);
    __half2 h23 = __floats2half2_rn(oz, ow);
    *(uint2*)(g_youth + zoff) = make_uint2(*(uint32_t*)&h01, *(uint32_t*)&h23);
}

extern "C" void kernel_launch(void* const* d_in, const int* in_sizes, int n_in,
                              void* d_out, int out_size)
{
    const float* X       = (const float*)d_in[0];
    const float* W_qkv   = (const float*)d_in[1];
    const float* W_z     = (const float*)d_in[2];
    const float* W_a     = (const float*)d_in[3];
    const float* W_b     = (const float*)d_in[4];
    const float* conv_w  = (const float*)d_in[5];
    const float* A_log   = (const float*)d_in[6];
    const float* dt_bias = (const float*)d_in[7];
    const float* norm_w  = (const float*)d_in[8];
    const float* W_out   = (const float*)d_in[9];

    float* out       = (float*)d_out;
    float* conv_st   = out + OUT_OFF_CONV;
    float* state_out = out + OUT_OFF_STATE;

    static float*  p_qkv_raw = nullptr;
    static float*  p_z = nullptr;
    static __half* p_xh = nullptr;
    static __half* p_wqkvh = nullptr;
    static __half* p_wzh = nullptr;
    static __half* p_wouth = nullptr;
    static __half* p_youth = nullptr;
    static cudaStream_t sB = nullptr, sC = nullptr;
    static cudaEvent_t evFork = nullptr, evAb = nullptr, evQkv0 = nullptr,
                       evQkv1 = nullptr, evZ = nullptr, evScan0 = nullptr,
                       evSide = nullptr;
    if (!p_qkv_raw) {
        cudaGetSymbolAddress((void**)&p_qkv_raw, g_qkv_raw);
        cudaGetSymbolAddress((void**)&p_z,       g_z);
        cudaGetSymbolAddress((void**)&p_xh,      g_xh);
        cudaGetSymbolAddress((void**)&p_wqkvh,   g_wqkvh);
        cudaGetSymbolAddress((void**)&p_wzh,     g_wzh);
        cudaGetSymbolAddress((void**)&p_wouth,   g_wouth);
        cudaGetSymbolAddress((void**)&p_youth,   g_youth);
        cudaStreamCreateWithFlags(&sB, cudaStreamNonBlocking);
        cudaStreamCreateWithFlags(&sC, cudaStreamNonBlocking);
        cudaEventCreateWithFlags(&evFork,  cudaEventDisableTiming);
        cudaEventCreateWithFlags(&evAb,    cudaEventDisableTiming);
        cudaEventCreateWithFlags(&evQkv0,  cudaEventDisableTiming);
        cudaEventCreateWithFlags(&evQkv1,  cudaEventDisableTiming);
        cudaEventCreateWithFlags(&evZ,     cudaEventDisableTiming);
        cudaEventCreateWithFlags(&evScan0, cudaEventDisableTiming);
        cudaEventCreateWithFlags(&evSide,  cudaEventDisableTiming);
    }

    // ---- fork: first captured node must be on the origin stream ----
    f2h_kernel<<<(BATCH*SEQ*HID)/1024, 256>>>(X, p_xh);
    cudaEventRecord(evFork, 0);
    cudaStreamWaitEvent(sB, evFork, 0);

    // ---- stream B: ab + W_z convert (hide under qkv(b0) chain) ----
    ab_kernel<<<(BATCH*SEQ)/4, 256, 0, sB>>>(X, W_a, W_b, A_log, dt_bias);
    cudaEventRecord(evAb, sB);
    f2h_kernel<<<(VDD*HID)/1024, 256, 0, sB>>>(W_z, p_wzh);

    // ---- main: W_qkv convert + qkv(b0) ----
    f2h_kernel<<<(CI*HID)/1024, 256>>>(W_qkv, p_wqkvh);
    gemm_h<<<dim3(16, CI/128), 128>>>(p_wqkvh, p_xh, p_qkv_raw, CI, BATCH*SEQ, HID, 1, 0);
    cudaEventRecord(evQkv0, 0);

    // ---- stream C (forked via evQkv0): qkv(b1) + convstate ----
    cudaStreamWaitEvent(sC, evQkv0, 0);
    gemm_h<<<dim3(16, CI/128), 128, 0, sC>>>(p_wqkvh, p_xh, p_qkv_raw, CI, BATCH*SEQ, HID, 1, SEQ);
    convstate_kernel<<<(BATCH*CI*KCONV)/256, 256, 0, sC>>>(conv_st);
    cudaEventRecord(evQkv1, sC);

    // ---- stream B: z projection + W_out convert (inside scan(b0) window) ----
    cudaStreamWaitEvent(sB, evQkv0, 0);
    gemm_h<<<dim3(VDD/128, (BATCH*SEQ)/128), 128, 0, sB>>>(p_xh, p_wzh, p_z, BATCH*SEQ, VDD, HID, 0, 0);
    f2h_kernel<<<(HID*VDD)/1024, 256, 0, sB>>>(W_out, p_wouth);
    cudaEventRecord(evZ, sB);

    // ---- main: batch-0 pipeline ----
    convnorm_kernel<<<dim3(SEQ/32, CI/128), 256>>>(conv_w, 0);
    cudaStreamWaitEvent(0, evAb, 0);
    scan_kernel<<<128, 128>>>(state_out, 0);
    cudaEventRecord(evScan0, 0);

    // ---- stream B: epilogue(b0) hidden under scan(b1) ----
    cudaStreamWaitEvent(sB, evScan0, 0);
    rms_gate_kernel<<<(SEQ*NVH)/8, 256, 0, sB>>>(norm_w, 0);
    gemm_h<<<dim3(HID/128, 16), 128, 0, sB>>>(p_youth, p_wouth, out, SEQ, HID, VDD, 0, 0);
    cudaEventRecord(evSide, sB);

    // ---- main: batch-1 pipeline ----
    cudaStreamWaitEvent(0, evQkv1, 0);
    convnorm_kernel<<<dim3(SEQ/32, CI/128), 256>>>(conv_w, 1);
    scan_kernel<<<128, 128>>>(state_out, 1);
    cudaStreamWaitEvent(0, evZ, 0);
    rms_gate_kernel<<<(SEQ*NVH)/8, 256>>>(norm_w, SEQ*NVH);
    gemm_h<<<dim3(HID/128, 16), 128>>>(p_youth + (size_t)SEQ*VDD, p_wouth,
                                       out + (size_t)SEQ*HID, SEQ, HID, VDD, 0, 0);

    // ---- join side streams before harness sync ----
    cudaStreamWaitEvent(0, evSide, 0);
}

// round 17
// speedup vs baseline: 1.9858x; 1.9858x over previous
#include <cuda_runtime.h>
#include <cuda_fp16.h>
#include <math.h>
#include <stdint.h>

#define BATCH    2
#define SEQ      2048
#define HID      2048
#define NKH      16
#define NVH      32
#define DKH      128
#define DVH      128
#define QKD      2048
#define VDD      4096
#define CI       8192
#define KCONV    4

#define OUT_OFF_CONV  (BATCH*SEQ*HID)
#define OUT_OFF_STATE (OUT_OFF_CONV + BATCH*CI*KCONV)

typedef unsigned long long u64;

__device__ float  g_qkv_raw[(size_t)BATCH*CI*SEQ];
__device__ float  g_conv   [(size_t)BATCH*SEQ*CI];
__device__ float  g_z      [(size_t)BATCH*SEQ*VDD];
__device__ float2 g_egbt   [(size_t)BATCH*SEQ*NVH];
__device__ float  g_y      [(size_t)BATCH*SEQ*NVH*DVH];
__device__ __half g_xh     [(size_t)BATCH*SEQ*HID];
__device__ __half g_wqkvh  [(size_t)CI*HID];
__device__ __half g_wzh    [(size_t)VDD*HID];
__device__ __half g_wouth  [(size_t)HID*VDD];
__device__ __half g_youth  [(size_t)BATCH*SEQ*VDD];

// ---------------- float -> half conversion ----------------
__global__ void f2h_kernel(const float* __restrict__ in, __half* __restrict__ out)
{
    size_t i = ((size_t)blockIdx.x * 256 + threadIdx.x) * 4;
    float4 v = *(const float4*)(in + i);
    __half2 a = __floats2half2_rn(v.x, v.y);
    __half2 b = __floats2half2_rn(v.z, v.w);
    *(uint2*)(out + i) = make_uint2(*(uint32_t*)&a, *(uint32_t*)&b);
}

// ------------------------------------------------------------------
// FP16 tensor-core GEMM, K-chunk 32, ldmatrix fragment loads.
// mode 0: C row-major. mode 1: C[b][m][s], n = b*SEQ+s.
// ------------------------------------------------------------------
__device__ __forceinline__ void mma_f16(float* c, const uint32_t* a, const uint32_t* b) {
    asm volatile(
        "mma.sync.aligned.m16n8k16.row.col.f32.f16.f16.f32 "
        "{%0,%1,%2,%3}, {%4,%5,%6,%7}, {%8,%9}, {%0,%1,%2,%3};"
        : "+f"(c[0]), "+f"(c[1]), "+f"(c[2]), "+f"(c[3])
        : "r"(a[0]), "r"(a[1]), "r"(a[2]), "r"(a[3]), "r"(b[0]), "r"(b[1]));
}

__device__ __forceinline__ void ldsm_x4(uint32_t* r, uint32_t addr) {
    asm volatile(
        "ldmatrix.sync.aligned.m8n8.x4.shared.b16 {%0,%1,%2,%3}, [%4];"
        : "=r"(r[0]), "=r"(r[1]), "=r"(r[2]), "=r"(r[3]) : "r"(addr));
}

__global__ __launch_bounds__(128, 2)
void gemm_h(const __half* __restrict__ A, const __half* __restrict__ Bm,
            float* __restrict__ C, int M, int N, int K, int mode)
{
    __shared__ uint32_t As[2][128][20];
    __shared__ uint32_t Bs[2][128][20];

    const int tid = threadIdx.x, lane = tid & 31, wid = tid >> 5;
    const int m0 = blockIdx.y * 128, n0 = blockIdx.x * 128;
    const int wm = (wid & 1) * 64, wn = (wid >> 1) * 64;

    const int lrow = tid >> 2;
    const int lc   = tid & 3;

    const __half* Ap = A  + (size_t)(m0 + lrow) * K + lc * 8;
    const __half* Bp = Bm + (size_t)(n0 + lrow) * K + lc * 8;

    const uint32_t asBase = (uint32_t)__cvta_generic_to_shared(&As[0][0][0]);
    const uint32_t bsBase = (uint32_t)__cvta_generic_to_shared(&Bs[0][0][0]);
    const uint32_t bufOff = 128 * 20 * 4;

    const int aRowOff = (wm + ((lane >> 3) & 1) * 8 + (lane & 7)) * 20
                      + ((lane >> 4) & 1) * 4;
    const int bRowOff = (wn + (lane >> 4) * 8 + (lane & 7)) * 20
                      + ((lane >> 3) & 1) * 4;

    float acc[4][8][4];
#pragma unroll
    for (int mi = 0; mi < 4; mi++)
#pragma unroll
        for (int ni = 0; ni < 8; ni++)
#pragma unroll
            for (int t = 0; t < 4; t++) acc[mi][ni][t] = 0.f;

    uint4 va[4], vb[4];
#pragma unroll
    for (int i = 0; i < 4; i++) {
        va[i] = *(const uint4*)(Ap + (size_t)(32 * i) * K);
        vb[i] = *(const uint4*)(Bp + (size_t)(32 * i) * K);
    }

    const int nch = K >> 5;

#pragma unroll
    for (int i = 0; i < 4; i++) {
        *(uint4*)&As[0][lrow + 32 * i][lc * 4] = va[i];
        *(uint4*)&Bs[0][lrow + 32 * i][lc * 4] = vb[i];
    }
    __syncthreads();

    const int g  = lane >> 2;
    const int kk = lane & 3;

    for (int c = 0; c < nch; c++) {
        const int buf = c & 1;
        const bool more = (c + 1 < nch);

        if (more) {
            const int ko = (c + 1) * 32;
#pragma unroll
            for (int i = 0; i < 4; i++) {
                va[i] = *(const uint4*)(Ap + (size_t)(32 * i) * K + ko);
                vb[i] = *(const uint4*)(Bp + (size_t)(32 * i) * K + ko);
            }
        }

        const uint32_t aB = asBase + buf * bufOff;
        const uint32_t bB = bsBase + buf * bufOff;

#pragma unroll
        for (int t = 0; t < 2; t++) {
            uint32_t af[4][4];
#pragma unroll
            for (int mi = 0; mi < 4; mi++)
                ldsm_x4(af[mi], aB + (uint32_t)(aRowOff + mi * 16 * 20 + t * 8) * 4);
            uint32_t bf[8][2];
#pragma unroll
            for (int p = 0; p < 4; p++) {
                uint32_t br[4];
                ldsm_x4(br, bB + (uint32_t)(bRowOff + p * 16 * 20 + t * 8) * 4);
                bf[2*p][0]   = br[0];
                bf[2*p][1]   = br[1];
                bf[2*p+1][0] = br[2];
                bf[2*p+1][1] = br[3];
            }
#pragma unroll
            for (int mi = 0; mi < 4; mi++)
#pragma unroll
                for (int ni = 0; ni < 8; ni++)
                    mma_f16(acc[mi][ni], af[mi], bf[ni]);
        }

        if (more) {
            const int ob = buf ^ 1;
#pragma unroll
            for (int i = 0; i < 4; i++) {
                *(uint4*)&As[ob][lrow + 32 * i][lc * 4] = va[i];
                *(uint4*)&Bs[ob][lrow + 32 * i][lc * 4] = vb[i];
            }
        }
        __syncthreads();
    }

#pragma unroll
    for (int mi = 0; mi < 4; mi++) {
        const int grow = m0 + wm + mi * 16 + g;
#pragma unroll
        for (int ni = 0; ni < 8; ni++) {
            const int gcol = n0 + wn + ni * 8 + kk * 2;
            if (mode == 0) {
                *(float2*)(C + (size_t)grow * N + gcol) =
                    make_float2(acc[mi][ni][0], acc[mi][ni][1]);
                *(float2*)(C + (size_t)(grow + 8) * N + gcol) =
                    make_float2(acc[mi][ni][2], acc[mi][ni][3]);
            } else {
                const int bi = gcol >> 11;
                const int sc = gcol & 2047;
                float* base = C + (size_t)bi * M * SEQ + sc;
                *(float2*)(base + (size_t)grow * SEQ) =
                    make_float2(acc[mi][ni][0], acc[mi][ni][1]);
                *(float2*)(base + (size_t)(grow + 8) * SEQ) =
                    make_float2(acc[mi][ni][2], acc[mi][ni][3]);
            }
        }
    }
}

// ------------------------------------------------------------------
__global__ __launch_bounds__(256)
void ab_kernel(const float* __restrict__ X, const float* __restrict__ Wa,
               const float* __restrict__ Wb, const float* __restrict__ A_log,
               const float* __restrict__ dt_bias)
{
    __shared__ float xs[4][HID];
    const int row0 = blockIdx.x * 4;
    for (int i = threadIdx.x; i < 4 * HID; i += 256)
        xs[i >> 11][i & 2047] = X[(size_t)(row0 + (i >> 11)) * HID + (i & 2047)];
    __syncthreads();

    const int w = threadIdx.x >> 5;
    const int lane = threadIdx.x & 31;
#pragma unroll 1
    for (int oi = 0; oi < 8; oi++) {
        int n = w * 8 + oi;
        const float* Wp = (n < 32) ? (Wa + (size_t)n * HID) : (Wb + (size_t)(n - 32) * HID);
        float a0 = 0.f, a1 = 0.f, a2 = 0.f, a3 = 0.f;
        for (int i = lane; i < HID; i += 32) {
            float wv = Wp[i];
            a0 = fmaf(xs[0][i], wv, a0);
            a1 = fmaf(xs[1][i], wv, a1);
            a2 = fmaf(xs[2][i], wv, a2);
            a3 = fmaf(xs[3][i], wv, a3);
        }
#pragma unroll
        for (int off = 16; off; off >>= 1) {
            a0 += __shfl_xor_sync(0xffffffffu, a0, off);
            a1 += __shfl_xor_sync(0xffffffffu, a1, off);
            a2 += __shfl_xor_sync(0xffffffffu, a2, off);
            a3 += __shfl_xor_sync(0xffffffffu, a3, off);
        }
        if (lane == 0) {
            float av[4] = {a0, a1, a2, a3};
            if (n < 32) {
                float al = expf(A_log[n]);
                float db = dt_bias[n];
#pragma unroll
                for (int r = 0; r < 4; r++) {
                    float x = av[r] + db;
                    float sp = (x > 20.f) ? x : log1pf(expf(x));
                    g_egbt[(size_t)(row0 + r) * NVH + n].x = expf(-al * sp);
                }
            } else {
#pragma unroll
                for (int r = 0; r < 4; r++)
                    g_egbt[(size_t)(row0 + r) * NVH + (n - 32)].y = 1.f / (1.f + expf(-av[r]));
            }
        }
    }
}

__global__ void convstate_kernel(float* __restrict__ outc)
{
    int idx = blockIdx.x * 256 + threadIdx.x;
    int b = idx >> 15;
    int rem = idx & 32767;
    int c = rem >> 2;
    int jj = rem & 3;
    outc[idx] = g_qkv_raw[(size_t)b * CI * SEQ + (size_t)c * SEQ + (SEQ - KCONV) + jj];
}

__global__ __launch_bounds__(256)
void convnorm_kernel(const float* __restrict__ w)
{
    __shared__ float in_sm[128][37];
    __shared__ float out_sm[32][132];
    const int s0 = blockIdx.x * 32;
    const int cb = blockIdx.y;
    const int c0 = cb * 128;
    const int b  = blockIdx.z;
    const float* rp = g_qkv_raw + (size_t)b * CI * SEQ + (size_t)c0 * SEQ;

    for (int idx = threadIdx.x; idx < 128 * 35; idx += 256) {
        int cl = idx / 35, sl = idx % 35;
        int s = s0 - 3 + sl;
        in_sm[cl][sl] = (s >= 0) ? rp[(size_t)cl * SEQ + s] : 0.f;
    }
    __syncthreads();

    {
        const int cl = threadIdx.x & 127;
        const int sh = threadIdx.x >> 7;
        const int c  = c0 + cl;
        const float w0 = w[c*4+0], w1 = w[c*4+1], w2 = w[c*4+2], w3 = w[c*4+3];
#pragma unroll
        for (int i = 0; i < 16; i++) {
            int sl = sh * 16 + i;
            float acc = in_sm[cl][sl] * w0 + in_sm[cl][sl+1] * w1
                      + in_sm[cl][sl+2] * w2 + in_sm[cl][sl+3] * w3;
            out_sm[sl][cl] = acc / (1.f + expf(-acc));
        }
    }
    __syncthreads();

    const int wld = threadIdx.x >> 5;
    const int lane = threadIdx.x & 31;
    const bool isqk = (cb < 32);
    const float qs = (cb < 16) ? 0.08838834764831845f : 1.0f;
    float* gout = g_conv + (size_t)b * SEQ * CI + c0;
#pragma unroll
    for (int t = 0; t < 4; t++) {
        int sl = wld * 4 + t;
        float4 v4 = *(float4*)&out_sm[sl][lane * 4];
        if (isqk) {
            float ss = v4.x*v4.x + v4.y*v4.y + v4.z*v4.z + v4.w*v4.w;
#pragma unroll
            for (int off = 16; off; off >>= 1) ss += __shfl_xor_sync(0xffffffffu, ss, off);
            float r = rsqrtf(ss + 1e-6f) * qs;
            v4.x *= r; v4.y *= r; v4.z *= r; v4.w *= r;
        }
        *(float4*)(gout + (size_t)(s0 + sl) * CI + lane * 4) = v4;
    }
}

// ------------------------------------------------------------------
// delta-rule scan (R11 config): 2 v-rows/thread, merged single
// shfl-tree reductions, f32x2 FMA, 2-step pipeline, full batch.
// ------------------------------------------------------------------
#define FMA2(d, a, b, c) \
    asm("fma.rn.f32x2 %0, %1, %2, %3;" : "=l"(d) : "l"(a), "l"(b), "l"(c))
#define MUL2(d, a, b) \
    asm("mul.rn.f32x2 %0, %1, %2;" : "=l"(d) : "l"(a), "l"(b))
#define PACK2(d, x) \
    asm("mov.b64 %0, {%1, %1};" : "=l"(d) : "r"(__float_as_uint(x)))
#define UNPACK2(lo, hi, s) \
    asm("mov.b64 {%0, %1}, %2;" : "=r"(lo), "=r"(hi) : "l"(s))

__device__ __forceinline__ float pairsum(u64 p) {
    uint32_t lo, hi;
    UNPACK2(lo, hi, p);
    return __uint_as_float(lo) + __uint_as_float(hi);
}

#define SCAN_LOAD(krp, qrp, vv, eb, s)                                          \
    do {                                                                        \
        const float* _rp = cb + (size_t)(s) * CI;                               \
        _Pragma("unroll")                                                       \
        for (int _g = 0; _g < 4; _g++) {                                        \
            *(ulonglong2*)((krp) + 2*_g) = *(const ulonglong2*)(_rp + koff + _g*32); \
            *(ulonglong2*)((qrp) + 2*_g) = *(const ulonglong2*)(_rp + qoff + _g*32); \
        }                                                                        \
        (vv) = *(const float2*)(_rp + voff);                                    \
        (eb) = ebp[(size_t)(s) * NVH];                                          \
    } while (0)

#define SCAN_STEP(krp, qrp, vv, eb, s)                                          \
    do {                                                                        \
        u64 kv0p = 0ull, kv1p = 0ull, qs0p = 0ull, qs1p = 0ull, qkp = 0ull;     \
        _Pragma("unroll")                                                       \
        for (int i = 0; i < 8; i++) {                                           \
            FMA2(kv0p, stp0[i], (krp)[i], kv0p);                                \
            FMA2(kv1p, stp1[i], (krp)[i], kv1p);                                \
            FMA2(qs0p, stp0[i], (qrp)[i], qs0p);                                \
            FMA2(qs1p, stp1[i], (qrp)[i], qs1p);                                \
            FMA2(qkp,  (krp)[i], (qrp)[i], qkp);                                \
        }                                                                        \
        float kv0 = pairsum(kv0p), kv1 = pairsum(kv1p);                         \
        float qs0 = pairsum(qs0p), qs1 = pairsum(qs1p);                         \
        float qk  = pairsum(qkp);                                               \
        _Pragma("unroll")                                                       \
        for (int off = 1; off <= 4; off <<= 1) {                                \
            kv0 += __shfl_xor_sync(0xffffffffu, kv0, off);                      \
            kv1 += __shfl_xor_sync(0xffffffffu, kv1, off);                      \
            qs0 += __shfl_xor_sync(0xffffffffu, qs0, off);                      \
            qs1 += __shfl_xor_sync(0xffffffffu, qs1, off);                      \
            qk  += __shfl_xor_sync(0xffffffffu, qk,  off);                      \
        }                                                                        \
        const float eg = (eb).x, bt = (eb).y;                                   \
        const float d0 = ((vv).x - eg * kv0) * bt;                              \
        const float d1 = ((vv).y - eg * kv1) * bt;                              \
        if (j == 0) {                                                           \
            float o0 = eg * qs0 + d0 * qk;                                      \
            float o1 = eg * qs1 + d1 * qk;                                      \
            *(float2*)(yp + (size_t)(s) * (NVH * 128)) = make_float2(o0, o1);   \
        }                                                                        \
        u64 egp, d0p, d1p;                                                      \
        PACK2(egp, eg);                                                         \
        PACK2(d0p, d0);                                                         \
        PACK2(d1p, d1);                                                         \
        _Pragma("unroll")                                                       \
        for (int i = 0; i < 8; i++) {                                           \
            u64 t0, t1;                                                         \
            MUL2(t0, (krp)[i], d0p);                                            \
            MUL2(t1, (krp)[i], d1p);                                            \
            FMA2(stp0[i], stp0[i], egp, t0);                                    \
            FMA2(stp1[i], stp1[i], egp, t1);                                    \
        }                                                                        \
    } while (0)

__global__ __launch_bounds__(128)
void scan_kernel(float* __restrict__ state_out)
{
    const int gt = blockIdx.x * 128 + threadIdx.x;   // 32768 threads
    const int j = gt & 7;
    const int rowi = gt >> 3;
    const int vp = rowi & 63;
    const int h = (rowi >> 6) & 31;
    const int b = rowi >> 11;
    const int kh = h >> 1;
    const int v0 = vp * 2;

    u64 stp0[8], stp1[8];
#pragma unroll
    for (int i = 0; i < 8; i++) { stp0[i] = 0ull; stp1[i] = 0ull; }

    const float* cb = g_conv + (size_t)b * SEQ * CI;
    const float2* ebp = g_egbt + (size_t)b * SEQ * NVH + h;
    const int qoff = kh * 128 + j * 4;
    const int koff = QKD + kh * 128 + j * 4;
    const int voff = 2 * QKD + h * 128 + v0;
    float* yp = g_y + ((size_t)b * SEQ * NVH + h) * 128 + v0;

    u64 krA[8], qrA[8], krB[8], qrB[8];
    float2 vvA, vvB, ebA, ebB;

    SCAN_LOAD(krA, qrA, vvA, ebA, 0);

    for (int s = 0; s < SEQ; s += 2) {
        SCAN_LOAD(krB, qrB, vvB, ebB, s + 1);
        SCAN_STEP(krA, qrA, vvA, ebA, s);
        if (s + 2 < SEQ) SCAN_LOAD(krA, qrA, vvA, ebA, s + 2);
        SCAN_STEP(krB, qrB, vvB, ebB, s + 1);
    }

    float* so0 = state_out + (((size_t)(b * NVH + h) * 128) + v0) * 128 + j * 4;
    float* so1 = so0 + 128;
#pragma unroll
    for (int g = 0; g < 4; g++) {
        *(ulonglong2*)(so0 + g * 32) = make_ulonglong2(stp0[2*g], stp0[2*g+1]);
        *(ulonglong2*)(so1 + g * 32) = make_ulonglong2(stp1[2*g], stp1[2*g+1]);
    }
}

__global__ __launch_bounds__(256)
void rms_gate_kernel(const float* __restrict__ nw)
{
    const int gidx = blockIdx.x * 8 + (threadIdx.x >> 5);
    const int lane = threadIdx.x & 31;
    const float* yv4 = g_y + (size_t)gidx * 128 + lane * 4;
    float4 yv = *(const float4*)yv4;
    float ss = yv.x*yv.x + yv.y*yv.y + yv.z*yv.z + yv.w*yv.w;
#pragma unroll
    for (int off = 16; off; off >>= 1) ss += __shfl_xor_sync(0xffffffffu, ss, off);
    const float r = rsqrtf(ss * (1.f / 128.f) + 1e-6f);
    const size_t zoff = ((size_t)(gidx >> 5)) * VDD + (size_t)(gidx & 31) * 128 + lane * 4;
    float4 zv = *(const float4*)(g_z + zoff);
    float4 nv = *(const float4*)(nw + lane * 4);
    float ox = nv.x * yv.x * r * (zv.x / (1.f + expf(-zv.x)));
    float oy = nv.y * yv.y * r * (zv.y / (1.f + expf(-zv.y)));
    float oz = nv.z * yv.z * r * (zv.z / (1.f + expf(-zv.z)));
    float ow = nv.w * yv.w * r * (zv.w / (1.f + expf(-zv.w)));
    __half2 h01 = __floats2half2_rn(ox, oy);
    __half2 h23 = __floats2half2_rn(oz, ow);
    *(uint2*)(g_youth + zoff) = make_uint2(*(uint32_t*)&h01, *(uint32_t*)&h23);
}

extern "C" void kernel_launch(void* const* d_in, const int* in_sizes, int n_in,
                              void* d_out, int out_size)
{
    const float* X       = (const float*)d_in[0];
    const float* W_qkv   = (const float*)d_in[1];
    const float* W_z     = (const float*)d_in[2];
    const float* W_a     = (const float*)d_in[3];
    const float* W_b     = (const float*)d_in[4];
    const float* conv_w  = (const float*)d_in[5];
    const float* A_log   = (const float*)d_in[6];
    const float* dt_bias = (const float*)d_in[7];
    const float* norm_w  = (const float*)d_in[8];
    const float* W_out   = (const float*)d_in[9];

    float* out       = (float*)d_out;
    float* conv_st   = out + OUT_OFF_CONV;
    float* state_out = out + OUT_OFF_STATE;

    static float*  p_qkv_raw = nullptr;
    static float*  p_z = nullptr;
    static __half* p_xh = nullptr;
    static __half* p_wqkvh = nullptr;
    static __half* p_wzh = nullptr;
    static __half* p_wouth = nullptr;
    static __half* p_youth = nullptr;
    static cudaStream_t sB = nullptr, sC = nullptr;
    static cudaEvent_t evFork = nullptr, evQkv = nullptr, evAb = nullptr,
                       evJoin = nullptr, evConvSt = nullptr;
    if (!p_qkv_raw) {
        cudaGetSymbolAddress((void**)&p_qkv_raw, g_qkv_raw);
        cudaGetSymbolAddress((void**)&p_z,       g_z);
        cudaGetSymbolAddress((void**)&p_xh,      g_xh);
        cudaGetSymbolAddress((void**)&p_wqkvh,   g_wqkvh);
        cudaGetSymbolAddress((void**)&p_wzh,     g_wzh);
        cudaGetSymbolAddress((void**)&p_wouth,   g_wouth);
        cudaGetSymbolAddress((void**)&p_youth,   g_youth);
        cudaStreamCreateWithFlags(&sB, cudaStreamNonBlocking);
        cudaStreamCreateWithFlags(&sC, cudaStreamNonBlocking);
        cudaEventCreateWithFlags(&evFork,   cudaEventDisableTiming);
        cudaEventCreateWithFlags(&evQkv,    cudaEventDisableTiming);
        cudaEventCreateWithFlags(&evAb,     cudaEventDisableTiming);
        cudaEventCreateWithFlags(&evJoin,   cudaEventDisableTiming);
        cudaEventCreateWithFlags(&evConvSt, cudaEventDisableTiming);
    }

    // main: X -> half (fork origin)
    f2h_kernel<<<(BATCH*SEQ*HID)/1024, 256>>>(X, p_xh);
    cudaEventRecord(evFork, 0);
    cudaStreamWaitEvent(sB, evFork, 0);

    // side B: a/b projections (hides under qkv GEMM), W_z convert
    ab_kernel<<<(BATCH*SEQ)/4, 256, 0, sB>>>(X, W_a, W_b, A_log, dt_bias);
    cudaEventRecord(evAb, sB);
    f2h_kernel<<<(VDD*HID)/1024, 256, 0, sB>>>(W_z, p_wzh);

    // main: qkv projection chain
    f2h_kernel<<<(CI*HID)/1024, 256>>>(W_qkv, p_wqkvh);
    gemm_h<<<dim3((BATCH*SEQ)/128, CI/128), 128>>>(p_wqkvh, p_xh, p_qkv_raw, CI, BATCH*SEQ, HID, 1);
    cudaEventRecord(evQkv, 0);

    // side C: conv_state copy (off critical path)
    cudaStreamWaitEvent(sC, evQkv, 0);
    convstate_kernel<<<(BATCH*CI*KCONV)/256, 256, 0, sC>>>(conv_st);
    cudaEventRecord(evConvSt, sC);

    // side B: z projection + W_out convert, scheduled into convnorm+scan window
    cudaStreamWaitEvent(sB, evQkv, 0);
    gemm_h<<<dim3(VDD/128, (BATCH*SEQ)/128), 128, 0, sB>>>(p_xh, p_wzh, p_z, BATCH*SEQ, VDD, HID, 0);
    f2h_kernel<<<(HID*VDD)/1024, 256, 0, sB>>>(W_out, p_wouth);
    cudaEventRecord(evJoin, sB);

    // main: conv chain + scan
    convnorm_kernel<<<dim3(SEQ/32, CI/128, BATCH), 256>>>(conv_w);
    cudaStreamWaitEvent(0, evAb, 0);
    scan_kernel<<<256, 128>>>(state_out);

    // join + epilogue
    cudaStreamWaitEvent(0, evJoin, 0);
    rms_gate_kernel<<<(BATCH*SEQ*NVH)/8, 256>>>(norm_w);
    gemm_h<<<dim3(HID/128, (BATCH*SEQ)/128), 128>>>(p_youth, p_wouth, out, BATCH*SEQ, HID, VDD, 0);
    cudaStreamWaitEvent(0, evConvSt, 0);
}